// round 13
// baseline (speedup 1.0000x reference)
#include <cuda_runtime.h>
#include <cuda_fp16.h>
#include <cstdint>

#define BATCH 256
#define SEQ   128
#define HID   1024
#define EMBD  300
#define OUTD  20
#define CAT   1324
#define KE    320
#define KEP   160      // packed uints per row (KE/2)
#define HP    512      // packed uints per HID row
#define NROWS 32768
#define PCTA  128

// ---------------- static device scratch ----------------
// packed fp16 pairs along k: uint32 = (elem 2j low16, elem 2j+1 high16)
__device__ float    g_c32[BATCH*HID];
__device__ unsigned g_Chp [BATCH*HID/2], g_Clp [BATCH*HID/2];
__device__ unsigned g_RChp[BATCH*HID/2], g_RClp[BATCH*HID/2];
__device__ float    g_u  [BATCH*HID];
__device__ float    g_X  [3L*SEQ*BATCH*HID];
__device__ unsigned g_Wruhp[2048L*HP], g_Wrulp[2048L*HP];
__device__ unsigned g_Wchp [1024L*HP], g_Wclp [1024L*HP];
__device__ unsigned g_Wxhp [3L*HID*KEP], g_Wxlp[3L*HID*KEP];
__device__ unsigned g_xehp [(long)NROWS*KEP], g_xelp[(long)NROWS*KEP];
__device__ unsigned g_barcnt;

#define LSCALE 2048.0f
#define LINV   (1.0f/2048.0f)

// ---------------- helpers ----------------
__device__ __forceinline__ unsigned packh2(float a, float b){
    __half2 h = __floats2half2_rn(a, b);
    return *reinterpret_cast<unsigned*>(&h);
}
__device__ __forceinline__ void split_pair(float v0, float v1, unsigned& hi, unsigned& lo){
    float h0 = __half2float(__float2half_rn(v0));
    float h1 = __half2float(__float2half_rn(v1));
    hi = packh2(h0, h1);
    lo = packh2((v0 - h0)*LSCALE, (v1 - h1)*LSCALE);
}
__device__ __forceinline__ void mma_f16(float c[4], const unsigned a[4], const unsigned b[2]){
    asm volatile("mma.sync.aligned.m16n8k16.row.col.f32.f16.f16.f32 "
        "{%0,%1,%2,%3},{%4,%5,%6,%7},{%8,%9},{%0,%1,%2,%3};"
        : "+f"(c[0]),"+f"(c[1]),"+f"(c[2]),"+f"(c[3])
        : "r"(a[0]),"r"(a[1]),"r"(a[2]),"r"(a[3]),"r"(b[0]),"r"(b[1]));
}
__device__ __forceinline__ void cp16(uint32_t d, const void* s){
    asm volatile("cp.async.cg.shared.global [%0], [%1], 16;" :: "r"(d), "l"(s));
}
#define CP_COMMIT asm volatile("cp.async.commit_group;")
#define CP_WAIT1  asm volatile("cp.async.wait_group 1;")

#define ST 20   // smem row stride in uints: 16 data + 4 pad -> conflict-free frag LDS

// ---------------- weight prefetch for stages 0,1 (issued pre-barrier) --------
// Geometry must match the gemm16<MT,NT> call that follows.
template<int MT, int NT>
__device__ __forceinline__ void prefetchB(char* sm,
    const unsigned* __restrict__ Bh, const unsigned* __restrict__ Bl,
    int ldbp, int n0)
{
    constexpr int AR  = MT*32;
    constexpr int BR  = NT*32;
    constexpr int OBH = 2*AR*ST;
    constexpr int OBL = OBH + BR*ST;
    constexpr int STG = OBL + BR*ST;
    const int tid = threadIdx.x;
    uint32_t smb = (uint32_t)__cvta_generic_to_shared(sm);
    #pragma unroll
    for (int buf=0; buf<2; ++buf){
        const int kk = buf*16;
        const uint32_t pb = smb + (uint32_t)buf*STG*4;
        for (int idx = tid; idx < BR*4; idx += 256){
            int r = idx>>2, c = idx&3;
            size_t off = (size_t)(n0+r)*ldbp + kk + c*4;
            cp16(pb + (uint32_t)(OBH + r*ST + c*4)*4,  Bh + off);
            cp16(pb + (uint32_t)(OBL + r*ST + c*4)*4,  Bl + off);
        }
    }
    CP_COMMIT;
}

// ---------------- GEMM core: (MT*32) x (NT*32) tile, K chunks of 32, 8 warps 2x4
// C[m,n] = sum_k A[m,k]*B[n,k]; operands fp16 hi / scaled-lo, packed pairs on k.
// accH = hi*hi; accM = lo*hi + hi*lo (scaled 2^11). 3-stage cp.async pipeline.
// PRE: B-parts of stages 0,1 were already issued via prefetchB (one older group);
//      A-parts of stages 0 and 1 are committed as SEPARATE groups so wait_group 1
//      at iter 0 guarantees stage 0 (preB + A0) fully resident.
template<int MT, int NT, bool PRE>
__device__ __forceinline__ void gemm16(char* sm,
    const unsigned* __restrict__ Ah, const unsigned* __restrict__ Al, int ldp,
    const unsigned* __restrict__ Bh, const unsigned* __restrict__ Bl, int ldbp,
    int m0, int n0, int K, float accH[MT][NT][4], float accM[MT][NT][4])
{
    constexpr int AR  = MT*32;
    constexpr int BR  = NT*32;
    constexpr int OAL = AR*ST;
    constexpr int OBH = 2*AR*ST;
    constexpr int OBL = OBH + BR*ST;
    constexpr int STG = OBL + BR*ST;      // uints per stage
    const int tid = threadIdx.x, lane = tid&31, warp = tid>>5;
    const int wm = warp>>2, wn = warp&3;
    const int lr = lane>>2, lc = lane&3;
    uint32_t smb = (uint32_t)__cvta_generic_to_shared(sm);
    const unsigned* smu = (const unsigned*)sm;

    #pragma unroll
    for (int i=0;i<MT;i++)
      #pragma unroll
      for (int j=0;j<NT;j++)
        #pragma unroll
        for (int e=0;e<4;e++){ accH[i][j][e]=0.f; accM[i][j][e]=0.f; }

    auto fillA = [&](int ki, int buf){
        const int kk = ki*16;
        const uint32_t pb = smb + (uint32_t)buf*STG*4;
        for (int idx = tid; idx < AR*4; idx += 256){
            int r = idx>>2, c = idx&3;
            size_t off = (size_t)(m0+r)*ldp + kk + c*4;
            cp16(pb + (uint32_t)(r*ST + c*4)*4,        Ah + off);
            cp16(pb + (uint32_t)(OAL + r*ST + c*4)*4,  Al + off);
        }
    };
    auto fillB = [&](int ki, int buf){
        const int kk = ki*16;
        const uint32_t pb = smb + (uint32_t)buf*STG*4;
        for (int idx = tid; idx < BR*4; idx += 256){
            int r = idx>>2, c = idx&3;
            size_t off = (size_t)(n0+r)*ldbp + kk + c*4;
            cp16(pb + (uint32_t)(OBH + r*ST + c*4)*4,  Bh + off);
            cp16(pb + (uint32_t)(OBL + r*ST + c*4)*4,  Bl + off);
        }
    };

    const int nk = K/32;
    if (PRE){
        fillA(0,0); CP_COMMIT;                    // stage-0 A (own group!)
        fillA(1,1); CP_COMMIT;                    // stage-1 A
    } else {
        fillA(0,0); fillB(0,0); CP_COMMIT;
        fillA(1,1); fillB(1,1); CP_COMMIT;
    }

    for (int i=0;i<nk;i++){
        CP_WAIT1;
        __syncthreads();
        if (i+2 < nk){ fillA(i+2,(i+2)%3); fillB(i+2,(i+2)%3); }
        CP_COMMIT;
        const unsigned* p = smu + (i%3)*STG;
        unsigned ah[2][MT][4], al[2][MT][4], bh[2][NT][2], bl[2][NT][2];
        #pragma unroll
        for (int s=0;s<2;s++){
            const unsigned* q = p + s*8;
            #pragma unroll
            for (int mt=0; mt<MT; mt++){
                const int R = (wm*MT + mt)*16;
                ah[s][mt][0] = q[(R+lr)*ST   + lc];
                ah[s][mt][1] = q[(R+8+lr)*ST + lc];
                ah[s][mt][2] = q[(R+lr)*ST   + 4+lc];
                ah[s][mt][3] = q[(R+8+lr)*ST + 4+lc];
                al[s][mt][0] = q[OAL + (R+lr)*ST   + lc];
                al[s][mt][1] = q[OAL + (R+8+lr)*ST + lc];
                al[s][mt][2] = q[OAL + (R+lr)*ST   + 4+lc];
                al[s][mt][3] = q[OAL + (R+8+lr)*ST + 4+lc];
            }
            #pragma unroll
            for (int nt=0; nt<NT; nt++){
                const int N = (wn*NT + nt)*8;
                bh[s][nt][0] = q[OBH + (N+lr)*ST + lc];
                bh[s][nt][1] = q[OBH + (N+lr)*ST + 4+lc];
                bl[s][nt][0] = q[OBL + (N+lr)*ST + lc];
                bl[s][nt][1] = q[OBL + (N+lr)*ST + 4+lc];
            }
        }
        // 6 passes; dependent accM updates kept apart
        #pragma unroll
        for (int mt=0; mt<MT; mt++)
          #pragma unroll
          for (int nt=0; nt<NT; nt++) mma_f16(accH[mt][nt], ah[0][mt], bh[0][nt]);
        #pragma unroll
        for (int mt=0; mt<MT; mt++)
          #pragma unroll
          for (int nt=0; nt<NT; nt++) mma_f16(accM[mt][nt], al[0][mt], bh[0][nt]);
        #pragma unroll
        for (int mt=0; mt<MT; mt++)
          #pragma unroll
          for (int nt=0; nt<NT; nt++) mma_f16(accH[mt][nt], ah[1][mt], bh[1][nt]);
        #pragma unroll
        for (int mt=0; mt<MT; mt++)
          #pragma unroll
          for (int nt=0; nt<NT; nt++) mma_f16(accM[mt][nt], ah[0][mt], bl[0][nt]);
        #pragma unroll
        for (int mt=0; mt<MT; mt++)
          #pragma unroll
          for (int nt=0; nt<NT; nt++) mma_f16(accM[mt][nt], al[1][mt], bh[1][nt]);
        #pragma unroll
        for (int mt=0; mt<MT; mt++)
          #pragma unroll
          for (int nt=0; nt<NT; nt++) mma_f16(accM[mt][nt], ah[1][mt], bl[1][nt]);
    }
    __syncthreads();
}

// ---------------- grid barrier (release/acquire, monotonic counter) -----------
__device__ __forceinline__ void gridbar(unsigned& nbar){
    __threadfence();
    __syncthreads();
    ++nbar;
    if (threadIdx.x == 0){
        asm volatile("red.release.gpu.global.add.u32 [%0], 1;" :: "l"(&g_barcnt) : "memory");
        const unsigned target = (unsigned)PCTA * nbar;
        unsigned v;
        do {
            asm volatile("ld.acquire.gpu.global.u32 %0, [%1];" : "=r"(v) : "l"(&g_barcnt) : "memory");
        } while (v < target);
    }
    __syncthreads();
}

// ---------------- prep kernels ----------------
__global__ void k_init(float* __restrict__ out, const float* __restrict__ bp){
    const long nout = (long)BATCH*SEQ*OUTD;
    for (long i = blockIdx.x*(long)blockDim.x + threadIdx.x; i < nout;
         i += (long)gridDim.x*blockDim.x){
        out[i] = bp[i % OUTD];
        if (i < (long)BATCH*HID) g_c32[i] = 0.f;
        if (i < (long)BATCH*HID/2){ g_Chp[i] = 0u; g_Clp[i] = 0u; }
        if (i == 0) g_barcnt = 0u;
    }
}

__global__ void k_prep(const float* __restrict__ Wr, const float* __restrict__ Wu,
                       const float* __restrict__ Wc){
    const long N1 = 2048L*HP, N2 = 1024L*HP, N3 = 3L*HID*KEP;
    for (long i = blockIdx.x*(long)blockDim.x + threadIdx.x; i < N1+N2+N3;
         i += (long)gridDim.x*blockDim.x){
        float v0, v1; unsigned *dh, *dl; long j;
        if (i < N1){
            j = i; int n = (int)(j/HP), kp = (int)(j - (long)n*HP);
            const float* W = (n < 1024) ? Wr : Wu;
            int nn = (n < 1024) ? n : n-1024;
            v0 = W[(long)nn*CAT + 2*kp];
            v1 = W[(long)nn*CAT + 2*kp+1];
            dh = g_Wruhp; dl = g_Wrulp;
        } else if (i < N1+N2){
            j = i - N1; int n = (int)(j/HP), kp = (int)(j - (long)n*HP);
            v0 = Wc[(long)n*CAT + 2*kp];
            v1 = Wc[(long)n*CAT + 2*kp+1];
            dh = g_Wchp; dl = g_Wclp;
        } else {
            j = i - N1 - N2; int n = (int)(j/KEP), kp = (int)(j - (long)n*KEP);
            int g = n / HID, h = n - g*HID;
            const float* W = (g==0)?Wr:((g==1)?Wu:Wc);
            int k0 = 2*kp, k1 = 2*kp+1;
            v0 = (k0 < EMBD) ? W[(long)h*CAT + HID + k0] : 0.f;
            v1 = (k1 < EMBD) ? W[(long)h*CAT + HID + k1] : 0.f;
            dh = g_Wxhp; dl = g_Wxlp;
        }
        unsigned hi, lo; split_pair(v0, v1, hi, lo);
        dh[j] = hi; dl[j] = lo;
    }
}

__global__ void k_gather(const int* __restrict__ x, const float* __restrict__ emb){
    const long total = (long)NROWS*KEP;
    for (long i = blockIdx.x*(long)blockDim.x + threadIdx.x; i < total;
         i += (long)gridDim.x*blockDim.x){
        int r = (int)(i/KEP), kp = (int)(i - (long)r*KEP);
        int k0 = 2*kp, k1 = 2*kp+1;
        const float* er = emb + (size_t)x[r]*EMBD;
        float v0 = (k0 < EMBD) ? er[k0] : 0.f;
        float v1 = (k1 < EMBD) ? er[k1] : 0.f;
        unsigned hi, lo; split_pair(v0, v1, hi, lo);
        g_xehp[i] = hi; g_xelp[i] = lo;
    }
}

// ---------------- x-part GEMM: [32768,320] x [320, 3x1024] (+bias) -----------
extern __shared__ char dynsm[];

__global__ void __launch_bounds__(256) k_xgemm(const float* __restrict__ br,
        const float* __restrict__ bu, const float* __restrict__ bc){
    float accH[2][2][4], accM[2][2][4];
    const int m0  = blockIdx.x*64;
    const int n0g = blockIdx.y*64;
    const int g   = n0g >> 10;
    const int n0  = n0g & 1023;
    gemm16<2,2,false>(dynsm, g_xehp, g_xelp, KEP,
                g_Wxhp + (size_t)g*HID*KEP, g_Wxlp + (size_t)g*HID*KEP, KEP,
                m0, n0, KE, accH, accM);
    const float* bias = (g==0)?br:((g==1)?bu:bc);
    float* Xg = g_X + (size_t)g*SEQ*BATCH*HID;
    const int lane = threadIdx.x&31, warp = threadIdx.x>>5;
    const int wm = warp>>2, wn = warp&3;
    #pragma unroll
    for (int mt=0;mt<2;mt++)
      #pragma unroll
      for (int nt=0;nt<2;nt++)
        #pragma unroll
        for (int ep=0;ep<2;ep++){
            const int r = m0 + (wm*2+mt)*16 + (lane>>2) + ep*8;
            const int c = n0 + (wn*2+nt)*8 + (lane&3)*2;
            const int b = r>>7, t = r&127;
            float2 o;
            o.x = accH[mt][nt][ep*2+0] + accM[mt][nt][ep*2+0]*LINV + bias[c];
            o.y = accH[mt][nt][ep*2+1] + accM[mt][nt][ep*2+1]*LINV + bias[c+1];
            *(float2*)(Xg + ((size_t)t*BATCH + b)*HID + c) = o;
        }
}

// ---------------- persistent recurrence: 128 CTAs x 256 threads (R8 tiling) ---
// Phase A (64x64): stage = (64+64)*2*20*4 = 20480B, x3 = 61440B.
// Phase B (32x64): stage = 15360B, x3 = 46080B (inside same window).
// Wps 20x64 f32 = 5120B at 61440; Cs 32x65 f32 = 8320B at 66560. Total 74880B.
#define SM_WPS 61440
#define SM_CS  66560
#define SM_TOT 74880

__global__ void __launch_bounds__(256,1) k_recur(float* __restrict__ out,
                                                 const float* __restrict__ Wp){
    char*  sm  = dynsm;
    float* Wps = (float*)(dynsm + SM_WPS);          // 20 x 64
    float* Cs  = (float*)(dynsm + SM_CS);           // 32 x 65
    const int cta = blockIdx.x;
    const int tid = threadIdx.x, lane = tid&31, warp = tid>>5;
    const int wm = warp>>2, wn = warp&3;

    const int mA = (cta&3)*64,  nA = (cta>>2)*64;   // 256x2048 as 4x32 tiles (64x64)
    const int mB = (cta&7)*32,  nB = (cta>>3)*64;   // 256x1024 as 8x16 tiles (32x64)

    for (int i = tid; i < OUTD*64; i += 256){
        int o = i>>6, hh = i&63;
        Wps[o*64+hh] = Wp[(size_t)o*HID + nB + hh];
    }
    __syncthreads();

    // deferred y-projection for step tt (reads Cs written at step tt's phase B)
    auto yproj = [&](int tt){
        const int bl = tid & 31, og = tid >> 5;
        #pragma unroll
        for (int j=og; j<OUTD; j+=8){
            float s = 0.f;
            #pragma unroll
            for (int hh=0; hh<64; ++hh)
                s += Cs[bl*65+hh] * Wps[j*64+hh];
            atomicAdd(&out[((size_t)(mB+bl)*SEQ + tt)*OUTD + j], s);
        }
    };

    unsigned nbar = 0;
    prefetchB<2,2>(sm, g_Wruhp, g_Wrulp, HP, nA);   // phase A weights, stages 0,1
    for (int t=0; t<SEQ; ++t){
        if (t > 0) yproj(t-1);                      // overlaps phase A fill window
        // ---- phase A: r,u gates (64x64, MT=2 NT=2) ----
        {
            float accH[2][2][4], accM[2][2][4];
            gemm16<2,2,true>(sm, g_Chp, g_Clp, HP, g_Wruhp, g_Wrulp, HP,
                             mA, nA, HID, accH, accM);
            prefetchB<1,2>(sm, g_Wchp, g_Wclp, HP, nB);   // phase B weights, pre-barrier
            const bool isU = (nA >= HID);
            const float* Xg = g_X + (size_t)((isU?1:0)*SEQ + t)*BATCH*HID;
            #pragma unroll
            for (int mt=0;mt<2;mt++)
              #pragma unroll
              for (int nt=0;nt<2;nt++)
                #pragma unroll
                for (int ep=0;ep<2;ep++){
                    const int b = mA + wm*32 + mt*16 + (lane>>2) + ep*8;
                    const int c = nA + wn*16 + nt*8 + (lane&3)*2;
                    const int h = c & (HID-1);
                    const size_t idx = (size_t)b*HID + h;
                    float2 xv = *(const float2*)(Xg + idx);
                    float p0 = accH[mt][nt][ep*2+0] + accM[mt][nt][ep*2+0]*LINV + xv.x;
                    float p1 = accH[mt][nt][ep*2+1] + accM[mt][nt][ep*2+1]*LINV + xv.y;
                    float s0 = 1.f/(1.f+__expf(-p0));
                    float s1 = 1.f/(1.f+__expf(-p1));
                    if (isU){
                        __stcg((float2*)(g_u+idx), make_float2(s0,s1));
                    } else {
                        float2 cp = __ldcg((const float2*)(g_c32+idx));
                        unsigned hi, lo; split_pair(s0*cp.x, s1*cp.y, hi, lo);
                        __stcg(&g_RChp[idx>>1], hi);
                        __stcg(&g_RClp[idx>>1], lo);
                    }
                }
        }
        gridbar(nbar);
        // ---- phase B: candidate + state update (32x64, MT=1 NT=2) ----
        {
            float accH[1][2][4], accM[1][2][4];
            gemm16<1,2,true>(sm, g_RChp, g_RClp, HP, g_Wchp, g_Wclp, HP,
                             mB, nB, HID, accH, accM);
            if (t+1 < SEQ)
                prefetchB<2,2>(sm, g_Wruhp, g_Wrulp, HP, nA);  // next step phase A
            const float* Xg = g_X + (size_t)(2*SEQ + t)*BATCH*HID;
            #pragma unroll
            for (int nt=0;nt<2;nt++)
              #pragma unroll
              for (int ep=0;ep<2;ep++){
                  const int b = mB + wm*16 + (lane>>2) + ep*8;
                  const int c = nB + wn*16 + nt*8 + (lane&3)*2;
                  const size_t idx = (size_t)b*HID + c;
                  float2 xv = *(const float2*)(Xg + idx);
                  float2 uv = __ldcg((const float2*)(g_u+idx));
                  float2 cp = __ldcg((const float2*)(g_c32+idx));
                  float cc0 = tanhf(accH[0][nt][ep*2+0] + accM[0][nt][ep*2+0]*LINV + xv.x);
                  float cc1 = tanhf(accH[0][nt][ep*2+1] + accM[0][nt][ep*2+1]*LINV + xv.y);
                  float cn0 = uv.x*cc0 + (1.f-uv.x)*cp.x;
                  float cn1 = uv.y*cc1 + (1.f-uv.y)*cp.y;
                  __stcg((float2*)(g_c32+idx), make_float2(cn0,cn1));
                  unsigned hi, lo; split_pair(cn0, cn1, hi, lo);
                  __stcg(&g_Chp[idx>>1], hi);
                  __stcg(&g_Clp[idx>>1], lo);
                  Cs[(b-mB)*65 + (c-nB)  ] = cn0;
                  Cs[(b-mB)*65 + (c-nB)+1] = cn1;
              }
        }
        gridbar(nbar);
    }
    yproj(SEQ-1);
}

// ---------------- launch ----------------
extern "C" void kernel_launch(void* const* d_in, const int* in_sizes, int n_in,
                              void* d_out, int out_size){
    const int*   x   = (const int*)  d_in[0];
    const float* emb = (const float*)d_in[1];
    const float* Wr  = (const float*)d_in[2];
    const float* br  = (const float*)d_in[3];
    const float* Wu  = (const float*)d_in[4];
    const float* bu  = (const float*)d_in[5];
    const float* Wc  = (const float*)d_in[6];
    const float* bc  = (const float*)d_in[7];
    const float* Wp  = (const float*)d_in[8];
    const float* bp  = (const float*)d_in[9];
    float* out = (float*)d_out;
    (void)in_sizes; (void)n_in; (void)out_size;

    static int attr_done = 0;
    if (!attr_done){
        cudaFuncSetAttribute(k_xgemm, cudaFuncAttributeMaxDynamicSharedMemorySize, 61440);
        cudaFuncSetAttribute(k_recur, cudaFuncAttributeMaxDynamicSharedMemorySize, SM_TOT);
        attr_done = 1;
    }

    k_init<<<512, 256>>>(out, bp);
    k_prep<<<1024, 256>>>(Wr, Wu, Wc);
    k_gather<<<2048, 256>>>(x, emb);
    k_xgemm<<<dim3(512,48), 256, 61440>>>(br, bu, bc);
    k_recur<<<PCTA, 256, SM_TOT>>>(out, Wp);
}

// round 15
// speedup vs baseline: 1.2686x; 1.2686x over previous
#include <cuda_runtime.h>
#include <cuda_fp16.h>
#include <cstdint>

#define BATCH 256
#define SEQ   128
#define HID   1024
#define EMBD  300
#define OUTD  20
#define CAT   1324
#define KE    320
#define KEP   160
#define HP    512
#define NROWS 32768
#define PCTA  128

// ---------------- static device scratch ----------------
__device__ float    g_c32[BATCH*HID];
__device__ float    g_u  [BATCH*HID];
__device__ float    g_X  [3L*SEQ*BATCH*HID];
// packed+swizzled operands for the recurrence (fp16 hi / scaled-lo pairs on k)
__device__ __align__(16) unsigned g_CPh [BATCH*HID/2], g_CPl [BATCH*HID/2];
__device__ __align__(16) unsigned g_RCPh[BATCH*HID/2], g_RCPl[BATCH*HID/2];
__device__ __align__(16) unsigned g_WruPh[2048L*HP], g_WruPl[2048L*HP];
__device__ __align__(16) unsigned g_WcPh [1024L*HP], g_WcPl [1024L*HP];
// xgemm operands (plain row-major packing, unchanged path)
__device__ __align__(16) unsigned g_Wxhp [3L*HID*KEP], g_Wxlp[3L*HID*KEP];
__device__ __align__(16) unsigned g_xehp [(long)NROWS*KEP], g_xelp[(long)NROWS*KEP];
__device__ unsigned g_barcnt;

#define LSCALE 2048.0f
#define LINV   (1.0f/2048.0f)

// ---------------- helpers ----------------
__device__ __forceinline__ unsigned packh2(float a, float b){
    __half2 h = __floats2half2_rn(a, b);
    return *reinterpret_cast<unsigned*>(&h);
}
__device__ __forceinline__ void split_pair(float v0, float v1, unsigned& hi, unsigned& lo){
    float h0 = __half2float(__float2half_rn(v0));
    float h1 = __half2float(__float2half_rn(v1));
    hi = packh2(h0, h1);
    lo = packh2((v0 - h0)*LSCALE, (v1 - h1)*LSCALE);
}
__device__ __forceinline__ void mma_f16(float c[4], const unsigned a[4], const unsigned b[2]){
    asm volatile("mma.sync.aligned.m16n8k16.row.col.f32.f16.f16.f32 "
        "{%0,%1,%2,%3},{%4,%5,%6,%7},{%8,%9},{%0,%1,%2,%3};"
        : "+f"(c[0]),"+f"(c[1]),"+f"(c[2]),"+f"(c[3])
        : "r"(a[0]),"r"(a[1]),"r"(a[2]),"r"(a[3]),"r"(b[0]),"r"(b[1]));
}
__device__ __forceinline__ void cp16(uint32_t d, const void* s){
    asm volatile("cp.async.cg.shared.global [%0], [%1], 16;" :: "r"(d), "l"(s));
}
#define CP_COMMIT asm volatile("cp.async.commit_group;")
#define CP_WAIT1  asm volatile("cp.async.wait_group 1;")

__device__ __forceinline__ void cpbulk(uint32_t dst, const void* src, unsigned bytes, uint32_t bar){
    asm volatile("cp.async.bulk.shared::cluster.global.mbarrier::complete_tx::bytes "
        "[%0], [%1], %2, [%3];"
        :: "r"(dst), "l"(src), "r"(bytes), "r"(bar) : "memory");
}
__device__ __forceinline__ void mbar_init(uint32_t bar, unsigned cnt){
    asm volatile("mbarrier.init.shared.b64 [%0], %1;" :: "r"(bar), "r"(cnt) : "memory");
}
__device__ __forceinline__ void mbar_expect(uint32_t bar, unsigned bytes){
    asm volatile("mbarrier.arrive.expect_tx.shared.b64 _, [%0], %1;"
        :: "r"(bar), "r"(bytes) : "memory");
}
__device__ __forceinline__ void mwait(uint32_t bar, unsigned parity){
    unsigned done;
    asm volatile("{\n\t.reg .pred p;\n\t"
        "mbarrier.try_wait.parity.acquire.cta.shared::cta.b64 p, [%1], %2;\n\t"
        "selp.b32 %0, 1, 0, p;\n\t}"
        : "=r"(done) : "r"(bar), "r"(parity) : "memory");
    if (!done){
        asm volatile("{\n\t.reg .pred P1;\n\t"
            "WL_%=:\n\t"
            "mbarrier.try_wait.parity.acquire.cta.shared::cta.b64 P1, [%0], %1, 0x989680;\n\t"
            "@P1 bra.uni WD_%=;\n\t"
            "bra.uni WL_%=;\n\t"
            "WD_%=:\n\t}"
            :: "r"(bar), "r"(parity) : "memory");
    }
}

// swizzled uint index within a packed block (row-pairs in 128B lines, chunk XOR by line)
__device__ __forceinline__ int swz(int row, int u){
    int L = row>>1;
    int ch = (((row&1)<<2) | (u>>2)) ^ (L&7);
    return (L<<5) + (ch<<2) + (u&3);
}

// ---------------- OLD gemm core (cp.async, row-major ST=20) — xgemm only ------
#define ST 20
template<int MT, int NT>
__device__ __forceinline__ void gemm16(char* sm,
    const unsigned* __restrict__ Ah, const unsigned* __restrict__ Al, int ldp,
    const unsigned* __restrict__ Bh, const unsigned* __restrict__ Bl, int ldbp,
    int m0, int n0, int K, float accH[MT][NT][4], float accM[MT][NT][4])
{
    constexpr int AR  = MT*32;
    constexpr int BR  = NT*32;
    constexpr int OAL = AR*ST;
    constexpr int OBH = 2*AR*ST;
    constexpr int OBL = OBH + BR*ST;
    constexpr int STG = OBL + BR*ST;
    const int tid = threadIdx.x, lane = tid&31, warp = tid>>5;
    const int wm = warp>>2, wn = warp&3;
    const int lr = lane>>2, lc = lane&3;
    uint32_t smb = (uint32_t)__cvta_generic_to_shared(sm);
    const unsigned* smu = (const unsigned*)sm;

    #pragma unroll
    for (int i=0;i<MT;i++)
      #pragma unroll
      for (int j=0;j<NT;j++)
        #pragma unroll
        for (int e=0;e<4;e++){ accH[i][j][e]=0.f; accM[i][j][e]=0.f; }

    auto fill = [&](int ki, int buf){
        const int kk = ki*16;
        const uint32_t pb = smb + (uint32_t)buf*STG*4;
        for (int idx = tid; idx < AR*4; idx += 256){
            int r = idx>>2, c = idx&3;
            size_t off = (size_t)(m0+r)*ldp + kk + c*4;
            cp16(pb + (uint32_t)(r*ST + c*4)*4,        Ah + off);
            cp16(pb + (uint32_t)(OAL + r*ST + c*4)*4,  Al + off);
        }
        for (int idx = tid; idx < BR*4; idx += 256){
            int r = idx>>2, c = idx&3;
            size_t off = (size_t)(n0+r)*ldbp + kk + c*4;
            cp16(pb + (uint32_t)(OBH + r*ST + c*4)*4,  Bh + off);
            cp16(pb + (uint32_t)(OBL + r*ST + c*4)*4,  Bl + off);
        }
    };

    const int nk = K/32;
    fill(0,0); CP_COMMIT;
    fill(1,1); CP_COMMIT;

    for (int i=0;i<nk;i++){
        CP_WAIT1;
        __syncthreads();
        if (i+2 < nk) fill(i+2, (i+2)%3);
        CP_COMMIT;
        const unsigned* p = smu + (i%3)*STG;
        unsigned ah[2][MT][4], al[2][MT][4], bh[2][NT][2], bl[2][NT][2];
        #pragma unroll
        for (int s=0;s<2;s++){
            const unsigned* q = p + s*8;
            #pragma unroll
            for (int mt=0; mt<MT; mt++){
                const int R = (wm*MT + mt)*16;
                ah[s][mt][0] = q[(R+lr)*ST   + lc];
                ah[s][mt][1] = q[(R+8+lr)*ST + lc];
                ah[s][mt][2] = q[(R+lr)*ST   + 4+lc];
                ah[s][mt][3] = q[(R+8+lr)*ST + 4+lc];
                al[s][mt][0] = q[OAL + (R+lr)*ST   + lc];
                al[s][mt][1] = q[OAL + (R+8+lr)*ST + lc];
                al[s][mt][2] = q[OAL + (R+lr)*ST   + 4+lc];
                al[s][mt][3] = q[OAL + (R+8+lr)*ST + 4+lc];
            }
            #pragma unroll
            for (int nt=0; nt<NT; nt++){
                const int N = (wn*NT + nt)*8;
                bh[s][nt][0] = q[OBH + (N+lr)*ST + lc];
                bh[s][nt][1] = q[OBH + (N+lr)*ST + 4+lc];
                bl[s][nt][0] = q[OBL + (N+lr)*ST + lc];
                bl[s][nt][1] = q[OBL + (N+lr)*ST + 4+lc];
            }
        }
        #pragma unroll
        for (int mt=0; mt<MT; mt++)
          #pragma unroll
          for (int nt=0; nt<NT; nt++) mma_f16(accH[mt][nt], ah[0][mt], bh[0][nt]);
        #pragma unroll
        for (int mt=0; mt<MT; mt++)
          #pragma unroll
          for (int nt=0; nt<NT; nt++) mma_f16(accM[mt][nt], al[0][mt], bh[0][nt]);
        #pragma unroll
        for (int mt=0; mt<MT; mt++)
          #pragma unroll
          for (int nt=0; nt<NT; nt++) mma_f16(accH[mt][nt], ah[1][mt], bh[1][nt]);
        #pragma unroll
        for (int mt=0; mt<MT; mt++)
          #pragma unroll
          for (int nt=0; nt<NT; nt++) mma_f16(accM[mt][nt], ah[0][mt], bl[0][nt]);
        #pragma unroll
        for (int mt=0; mt<MT; mt++)
          #pragma unroll
          for (int nt=0; nt<NT; nt++) mma_f16(accM[mt][nt], al[1][mt], bh[1][nt]);
        #pragma unroll
        for (int mt=0; mt<MT; mt++)
          #pragma unroll
          for (int nt=0; nt<NT; nt++) mma_f16(accM[mt][nt], ah[1][mt], bl[1][nt]);
    }
    __syncthreads();
}

// ---------------- NEW bulk-copy gemm core (recurrence) ----------------------
// Tile (MT*32) x 64, 8 warps 2x4, K=1024 in 32 chunks of 32.
// Operands packed+swizzled per kchunk block; A stride 4096 uints, B stride 1024.
// Stage buffers: 3 x 16KB at smem offset 0; mbarriers at mb (+8 per buffer).
template<int MT>
__device__ __forceinline__ void gemmBulk(char* sm, uint32_t mb,
    const unsigned* __restrict__ Ah, const unsigned* __restrict__ Al,
    const unsigned* __restrict__ Bh, const unsigned* __restrict__ Bl,
    int& nu0, int& nu1, int& nu2,
    float accH[MT][2][4], float accM[MT][2][4])
{
    constexpr int AU = MT*32*16;            // uints per A block
    constexpr unsigned TXB = 8u*AU + 8192u; // bytes per stage
    const int tid = threadIdx.x, lane = tid&31, warp = tid>>5;
    const int wm = warp>>2, wn = warp&3;
    const int lr = lane>>2, lc = lane&3;
    uint32_t smb = (uint32_t)__cvta_generic_to_shared(sm);
    const unsigned* smu = (const unsigned*)sm;

    int offA[2][MT][4], offB[2][2][2];
    #pragma unroll
    for (int s=0;s<2;s++){
        #pragma unroll
        for (int mt=0; mt<MT; mt++)
            #pragma unroll
            for (int j=0;j<4;j++){
                int row = (wm*MT + mt)*16 + ((j&1)<<3) + lr;
                int u = (s<<3) + ((j>>1)<<2) + lc;
                offA[s][mt][j] = swz(row, u);
            }
        #pragma unroll
        for (int nt=0; nt<2; nt++)
            #pragma unroll
            for (int j=0;j<2;j++){
                int row = wn*16 + nt*8 + lr;
                int u = (s<<3) + (j<<2) + lc;
                offB[s][nt][j] = swz(row, u);
            }
    }

    #pragma unroll
    for (int i=0;i<MT;i++)
      #pragma unroll
      for (int j=0;j<2;j++)
        #pragma unroll
        for (int e=0;e<4;e++){ accH[i][j][e]=0.f; accM[i][j][e]=0.f; }

    auto issue = [&](int ki, int buf){
        uint32_t bar = mb + (uint32_t)buf*8;
        uint32_t dst = smb + (uint32_t)buf*16384;
        mbar_expect(bar, TXB);
        cpbulk(dst,                   Ah + (size_t)ki*4096, AU*4, bar);
        cpbulk(dst + AU*4,            Al + (size_t)ki*4096, AU*4, bar);
        cpbulk(dst + 2*AU*4,          Bh + (size_t)ki*1024, 4096, bar);
        cpbulk(dst + 2*AU*4 + 4096,   Bl + (size_t)ki*1024, 4096, bar);
    };

    if (tid == 0){
        asm volatile("fence.proxy.async;" ::: "memory");
        issue(0,0); issue(1,1); issue(2,2);
    }

    auto doIter = [&](int ki, int buf, int& nu){
        mwait(mb + (uint32_t)buf*8, (unsigned)(nu & 1));
        nu++;
        const unsigned* base = smu + (size_t)buf*4096;
        unsigned ah[2][MT][4], al[2][MT][4], bh[2][2][2], bl[2][2][2];
        #pragma unroll
        for (int s=0;s<2;s++){
            #pragma unroll
            for (int mt=0;mt<MT;mt++)
                #pragma unroll
                for (int j=0;j<4;j++){
                    ah[s][mt][j] = base[offA[s][mt][j]];
                    al[s][mt][j] = base[AU + offA[s][mt][j]];
                }
            #pragma unroll
            for (int nt=0;nt<2;nt++)
                #pragma unroll
                for (int j=0;j<2;j++){
                    bh[s][nt][j] = base[2*AU + offB[s][nt][j]];
                    bl[s][nt][j] = base[2*AU + 1024 + offB[s][nt][j]];
                }
        }
        #pragma unroll
        for (int mt=0; mt<MT; mt++)
          #pragma unroll
          for (int nt=0; nt<2; nt++) mma_f16(accH[mt][nt], ah[0][mt], bh[0][nt]);
        #pragma unroll
        for (int mt=0; mt<MT; mt++)
          #pragma unroll
          for (int nt=0; nt<2; nt++) mma_f16(accM[mt][nt], al[0][mt], bh[0][nt]);
        #pragma unroll
        for (int mt=0; mt<MT; mt++)
          #pragma unroll
          for (int nt=0; nt<2; nt++) mma_f16(accH[mt][nt], ah[1][mt], bh[1][nt]);
        #pragma unroll
        for (int mt=0; mt<MT; mt++)
          #pragma unroll
          for (int nt=0; nt<2; nt++) mma_f16(accM[mt][nt], ah[0][mt], bl[0][nt]);
        #pragma unroll
        for (int mt=0; mt<MT; mt++)
          #pragma unroll
          for (int nt=0; nt<2; nt++) mma_f16(accM[mt][nt], al[1][mt], bh[1][nt]);
        #pragma unroll
        for (int mt=0; mt<MT; mt++)
          #pragma unroll
          for (int nt=0; nt<2; nt++) mma_f16(accM[mt][nt], ah[1][mt], bl[1][nt]);
        __syncthreads();
        if (tid == 0 && ki+3 < 32) issue(ki+3, buf);
    };

    for (int io=0; io<30; io+=3){
        doIter(io,   0, nu0);
        doIter(io+1, 1, nu1);
        doIter(io+2, 2, nu2);
    }
    doIter(30, 0, nu0);
    doIter(31, 1, nu1);
}

// ---------------- grid barrier ----------------
__device__ __forceinline__ void gridbar(unsigned& nbar){
    __threadfence();
    __syncthreads();
    ++nbar;
    if (threadIdx.x == 0){
        asm volatile("red.release.gpu.global.add.u32 [%0], 1;" :: "l"(&g_barcnt) : "memory");
        const unsigned target = (unsigned)PCTA * nbar;
        unsigned v;
        do {
            asm volatile("ld.acquire.gpu.global.u32 %0, [%1];" : "=r"(v) : "l"(&g_barcnt) : "memory");
        } while (v < target);
    }
    __syncthreads();
}

// ---------------- prep kernels ----------------
__global__ void k_init(float* __restrict__ out, const float* __restrict__ bp){
    const long nout = (long)BATCH*SEQ*OUTD;
    for (long i = blockIdx.x*(long)blockDim.x + threadIdx.x; i < nout;
         i += (long)gridDim.x*blockDim.x){
        out[i] = bp[i % OUTD];
        if (i < (long)BATCH*HID) g_c32[i] = 0.f;
        if (i < (long)BATCH*HID/2){ g_CPh[i] = 0u; g_CPl[i] = 0u; }
        if (i == 0) g_barcnt = 0u;
    }
}

__global__ void k_prep(const float* __restrict__ Wr, const float* __restrict__ Wu,
                       const float* __restrict__ Wc){
    const long N1 = 2048L*512;   // WruP packed uints
    const long N2 = 1024L*512;   // WcP
    const long N3 = 3L*HID*KEP;  // Wx plain
    for (long i = blockIdx.x*(long)blockDim.x + threadIdx.x; i < N1+N2+N3;
         i += (long)gridDim.x*blockDim.x){
        float v0, v1; unsigned *dh, *dl; long j;
        if (i < N1 + N2){
            const bool isRu = (i < N1);
            j = isRu ? i : (i - N1);
            int blk    = (int)(j>>10);
            int ntile  = blk>>5;
            int kch    = blk&31;
            int within = (int)(j&1023);
            int L = within>>5, chp = (within>>2)&7, w = within&3;
            int chunk = chp ^ (L&7);
            int row = (L<<1) | (chunk>>2);
            int u   = ((chunk&3)<<2) | w;
            int n   = ntile*64 + row;
            int k0  = kch*32 + u*2;
            const float* W; int nn;
            if (isRu){ W = (n < 1024) ? Wr : Wu; nn = (n < 1024) ? n : n-1024;
                       dh = g_WruPh; dl = g_WruPl; }
            else     { W = Wc; nn = n; dh = g_WcPh; dl = g_WcPl; }
            v0 = W[(long)nn*CAT + k0];
            v1 = W[(long)nn*CAT + k0+1];
        } else {
            j = i - N1 - N2;
            int n = (int)(j/KEP), kp = (int)(j - (long)n*KEP);
            int g = n / HID, h = n - g*HID;
            const float* W = (g==0)?Wr:((g==1)?Wu:Wc);
            int k0 = 2*kp, k1 = 2*kp+1;
            v0 = (k0 < EMBD) ? W[(long)h*CAT + HID + k0] : 0.f;
            v1 = (k1 < EMBD) ? W[(long)h*CAT + HID + k1] : 0.f;
            dh = g_Wxhp; dl = g_Wxlp;
        }
        unsigned hi, lo; split_pair(v0, v1, hi, lo);
        dh[j] = hi; dl[j] = lo;
    }
}

__global__ void k_gather(const int* __restrict__ x, const float* __restrict__ emb){
    const long total = (long)NROWS*KEP;
    for (long i = blockIdx.x*(long)blockDim.x + threadIdx.x; i < total;
         i += (long)gridDim.x*blockDim.x){
        int r = (int)(i/KEP), kp = (int)(i - (long)r*KEP);
        int k0 = 2*kp, k1 = 2*kp+1;
        const float* er = emb + (size_t)x[r]*EMBD;
        float v0 = (k0 < EMBD) ? er[k0] : 0.f;
        float v1 = (k1 < EMBD) ? er[k1] : 0.f;
        unsigned hi, lo; split_pair(v0, v1, hi, lo);
        g_xehp[i] = hi; g_xelp[i] = lo;
    }
}

// ---------------- x-part GEMM (unchanged path) ----------------
extern __shared__ char dynsm[];

__global__ void __launch_bounds__(256) k_xgemm(const float* __restrict__ br,
        const float* __restrict__ bu, const float* __restrict__ bc){
    float accH[2][2][4], accM[2][2][4];
    const int m0  = blockIdx.x*64;
    const int n0g = blockIdx.y*64;
    const int g   = n0g >> 10;
    const int n0  = n0g & 1023;
    gemm16<2,2>(dynsm, g_xehp, g_xelp, KEP,
                g_Wxhp + (size_t)g*HID*KEP, g_Wxlp + (size_t)g*HID*KEP, KEP,
                m0, n0, KE, accH, accM);
    const float* bias = (g==0)?br:((g==1)?bu:bc);
    float* Xg = g_X + (size_t)g*SEQ*BATCH*HID;
    const int lane = threadIdx.x&31, warp = threadIdx.x>>5;
    const int wm = warp>>2, wn = warp&3;
    #pragma unroll
    for (int mt=0;mt<2;mt++)
      #pragma unroll
      for (int nt=0;nt<2;nt++)
        #pragma unroll
        for (int ep=0;ep<2;ep++){
            const int r = m0 + (wm*2+mt)*16 + (lane>>2) + ep*8;
            const int c = n0 + (wn*2+nt)*8 + (lane&3)*2;
            const int b = r>>7, t = r&127;
            float2 o;
            o.x = accH[mt][nt][ep*2+0] + accM[mt][nt][ep*2+0]*LINV + bias[c];
            o.y = accH[mt][nt][ep*2+1] + accM[mt][nt][ep*2+1]*LINV + bias[c+1];
            *(float2*)(Xg + ((size_t)t*BATCH + b)*HID + c) = o;
        }
}

// ---------------- persistent recurrence: bulk-copy pipeline ------------------
// smem: 3 x 16KB stages [0, 49152) | mbarriers at 49152 | Wps 49216 | Cs 54336
#define SM_MBAR 49152
#define SM_WPS  49216
#define SM_CS   54336
#define SM_TOT  62656

__global__ void __launch_bounds__(256,1) k_recur(float* __restrict__ out,
                                                 const float* __restrict__ Wp){
    char*  sm  = dynsm;
    float* Wps = (float*)(dynsm + SM_WPS);          // 20 x 64
    float* Cs  = (float*)(dynsm + SM_CS);           // 32 x 65
    const int cta = blockIdx.x;
    const int tid = threadIdx.x, lane = tid&31, warp = tid>>5;
    const int wm = warp>>2, wn = warp&3;
    uint32_t smb = (uint32_t)__cvta_generic_to_shared(sm);
    const uint32_t mb = smb + SM_MBAR;

    const int mA = (cta&3)*64,  nA = (cta>>2)*64;   // phase A: 4m x 32n tiles (64x64)
    const int mB = (cta&7)*32,  nB = (cta>>3)*64;   // phase B: 8m x 16n tiles (32x64)

    if (tid == 0){
        mbar_init(mb,    1);
        mbar_init(mb+8,  1);
        mbar_init(mb+16, 1);
        asm volatile("fence.proxy.async;" ::: "memory");
    }
    for (int i = tid; i < OUTD*64; i += 256){
        int o = i>>6, hh = i&63;
        Wps[o*64+hh] = Wp[(size_t)o*HID + nB + hh];
    }
    __syncthreads();

    const unsigned* Aa_h = g_CPh  + (size_t)(cta&3)*1024;
    const unsigned* Aa_l = g_CPl  + (size_t)(cta&3)*1024;
    const unsigned* Ba_h = g_WruPh + (size_t)(cta>>2)*32768;
    const unsigned* Ba_l = g_WruPl + (size_t)(cta>>2)*32768;
    const unsigned* Ab_h = g_RCPh + (size_t)(cta&7)*512;
    const unsigned* Ab_l = g_RCPl + (size_t)(cta&7)*512;
    const unsigned* Bb_h = g_WcPh + (size_t)(cta>>3)*32768;
    const unsigned* Bb_l = g_WcPl + (size_t)(cta>>3)*32768;

    int nu0 = 0, nu1 = 0, nu2 = 0;
    unsigned nbar = 0;
    for (int t=0; t<SEQ; ++t){
        // ---- phase A: r,u gates (64x64, MT=2) ----
        {
            float accH[2][2][4], accM[2][2][4];
            gemmBulk<2>(sm, mb, Aa_h, Aa_l, Ba_h, Ba_l, nu0, nu1, nu2, accH, accM);
            const bool isU = (nA >= HID);
            const float* Xg = g_X + (size_t)((isU?1:0)*SEQ + t)*BATCH*HID;
            #pragma unroll
            for (int mt=0;mt<2;mt++)
              #pragma unroll
              for (int nt=0;nt<2;nt++)
                #pragma unroll
                for (int ep=0;ep<2;ep++){
                    const int b = mA + (wm*2+mt)*16 + (lane>>2) + ep*8;
                    const int c = nA + (wn*2+nt)*8 + (lane&3)*2;
                    const int h = c & (HID-1);
                    const size_t idx = (size_t)b*HID + h;
                    float2 xv = *(const float2*)(Xg + idx);
                    float p0 = accH[mt][nt][ep*2+0] + accM[mt][nt][ep*2+0]*LINV + xv.x;
                    float p1 = accH[mt][nt][ep*2+1] + accM[mt][nt][ep*2+1]*LINV + xv.y;
                    float s0 = 1.f/(1.f+__expf(-p0));
                    float s1 = 1.f/(1.f+__expf(-p1));
                    if (isU){
                        __stcg((float2*)(g_u+idx), make_float2(s0,s1));
                    } else {
                        float2 cp = __ldcg((const float2*)(g_c32+idx));
                        unsigned hi, lo; split_pair(s0*cp.x, s1*cp.y, hi, lo);
                        // packed RC layout: [kchunk][mtile8][512], swizzled
                        int kch = h>>5, mtl = b>>5, row = b&31, uu = (h&31)>>1;
                        size_t pidx = (size_t)(kch*8 + mtl)*512 + swz(row, uu);
                        __stcg(&g_RCPh[pidx], hi);
                        __stcg(&g_RCPl[pidx], lo);
                    }
                }
        }
        gridbar(nbar);
        // ---- phase B: candidate + state update + y (32x64, MT=1) ----
        {
            float accH[1][2][4], accM[1][2][4];
            gemmBulk<1>(sm, mb, Ab_h, Ab_l, Bb_h, Bb_l, nu0, nu1, nu2, accH, accM);
            const float* Xg = g_X + (size_t)(2*SEQ + t)*BATCH*HID;
            #pragma unroll
            for (int nt=0;nt<2;nt++)
              #pragma unroll
              for (int ep=0;ep<2;ep++){
                  const int b = mB + wm*16 + (lane>>2) + ep*8;
                  const int c = nB + (wn*2+nt)*8 + (lane&3)*2;
                  const size_t idx = (size_t)b*HID + c;
                  float2 xv = *(const float2*)(Xg + idx);
                  float2 uv = __ldcg((const float2*)(g_u+idx));
                  float2 cp = __ldcg((const float2*)(g_c32+idx));
                  float cc0 = tanhf(accH[0][nt][ep*2+0] + accM[0][nt][ep*2+0]*LINV + xv.x);
                  float cc1 = tanhf(accH[0][nt][ep*2+1] + accM[0][nt][ep*2+1]*LINV + xv.y);
                  float cn0 = uv.x*cc0 + (1.f-uv.x)*cp.x;
                  float cn1 = uv.y*cc1 + (1.f-uv.y)*cp.y;
                  __stcg((float2*)(g_c32+idx), make_float2(cn0,cn1));
                  unsigned hi, lo; split_pair(cn0, cn1, hi, lo);
                  // packed C layout: [kchunk][mtile4][1024], swizzled
                  int kch = c>>5, mtl = b>>6, row = b&63, uu = (c&31)>>1;
                  size_t pidx = (size_t)(kch*4 + mtl)*1024 + swz(row, uu);
                  __stcg(&g_CPh[pidx], hi);
                  __stcg(&g_CPl[pidx], lo);
                  Cs[(b-mB)*65 + (c-nB)  ] = cn0;
                  Cs[(b-mB)*65 + (c-nB)+1] = cn1;
              }
            __syncthreads();
            const int bl = tid & 31, og = tid >> 5;
            #pragma unroll
            for (int j=og; j<OUTD; j+=8){
                float s = 0.f;
                #pragma unroll
                for (int hh=0; hh<64; ++hh)
                    s += Cs[bl*65+hh] * Wps[j*64+hh];
                atomicAdd(&out[((size_t)(mB+bl)*SEQ + t)*OUTD + j], s);
            }
        }
        gridbar(nbar);
    }
}

// ---------------- launch ----------------
extern "C" void kernel_launch(void* const* d_in, const int* in_sizes, int n_in,
                              void* d_out, int out_size){
    const int*   x   = (const int*)  d_in[0];
    const float* emb = (const float*)d_in[1];
    const float* Wr  = (const float*)d_in[2];
    const float* br  = (const float*)d_in[3];
    const float* Wu  = (const float*)d_in[4];
    const float* bu  = (const float*)d_in[5];
    const float* Wc  = (const float*)d_in[6];
    const float* bc  = (const float*)d_in[7];
    const float* Wp  = (const float*)d_in[8];
    const float* bp  = (const float*)d_in[9];
    float* out = (float*)d_out;
    (void)in_sizes; (void)n_in; (void)out_size;

    static int attr_done = 0;
    if (!attr_done){
        cudaFuncSetAttribute(k_xgemm, cudaFuncAttributeMaxDynamicSharedMemorySize, 61440);
        cudaFuncSetAttribute(k_recur, cudaFuncAttributeMaxDynamicSharedMemorySize, SM_TOT);
        attr_done = 1;
    }

    k_init<<<512, 256>>>(out, bp);
    k_prep<<<1024, 256>>>(Wr, Wu, Wc);
    k_gather<<<2048, 256>>>(x, emb);
    k_xgemm<<<dim3(512,48), 256, 61440>>>(br, bu, bc);
    k_recur<<<PCTA, 256, SM_TOT>>>(out, Wp);
}

// round 17
// speedup vs baseline: 1.3181x; 1.0390x over previous
#include <cuda_runtime.h>
#include <cuda_fp16.h>
#include <cstdint>

#define BATCH 256
#define SEQ   128
#define HID   1024
#define EMBD  300
#define OUTD  20
#define CAT   1324
#define NROWS 32768
#define PCTA  128
#define XNK   10        // xgemm k-chunks (320 k / 32)

// ---------------- static device scratch ----------------
__device__ float    g_c32[BATCH*HID];
__device__ float    g_u  [BATCH*HID];
__device__ float    g_X  [3L*SEQ*BATCH*HID];
// packed+swizzled operands (fp16 hi / scaled-lo pairs on k, 1024-uint blocks)
__device__ __align__(16) unsigned g_CPh [BATCH*HID/2], g_CPl [BATCH*HID/2];
__device__ __align__(16) unsigned g_RCPh[BATCH*HID/2], g_RCPl[BATCH*HID/2];
__device__ __align__(16) unsigned g_WruPh[2048L*512], g_WruPl[2048L*512];
__device__ __align__(16) unsigned g_WcPh [1024L*512], g_WcPl [1024L*512];
__device__ __align__(16) unsigned g_WxPh [48L*XNK*1024], g_WxPl[48L*XNK*1024];
__device__ __align__(16) unsigned g_xePh [(long)512*XNK*1024], g_xePl[(long)512*XNK*1024];
__device__ unsigned g_barcnt;

#define LSCALE 2048.0f
#define LINV   (1.0f/2048.0f)

// ---------------- helpers ----------------
__device__ __forceinline__ unsigned packh2(float a, float b){
    __half2 h = __floats2half2_rn(a, b);
    return *reinterpret_cast<unsigned*>(&h);
}
__device__ __forceinline__ void split_pair(float v0, float v1, unsigned& hi, unsigned& lo){
    float h0 = __half2float(__float2half_rn(v0));
    float h1 = __half2float(__float2half_rn(v1));
    hi = packh2(h0, h1);
    lo = packh2((v0 - h0)*LSCALE, (v1 - h1)*LSCALE);
}
__device__ __forceinline__ void mma_f16(float c[4], const unsigned a[4], const unsigned b[2]){
    asm volatile("mma.sync.aligned.m16n8k16.row.col.f32.f16.f16.f32 "
        "{%0,%1,%2,%3},{%4,%5,%6,%7},{%8,%9},{%0,%1,%2,%3};"
        : "+f"(c[0]),"+f"(c[1]),"+f"(c[2]),"+f"(c[3])
        : "r"(a[0]),"r"(a[1]),"r"(a[2]),"r"(a[3]),"r"(b[0]),"r"(b[1]));
}
__device__ __forceinline__ void cpbulk(uint32_t dst, const void* src, unsigned bytes, uint32_t bar){
    asm volatile("cp.async.bulk.shared::cluster.global.mbarrier::complete_tx::bytes "
        "[%0], [%1], %2, [%3];"
        :: "r"(dst), "l"(src), "r"(bytes), "r"(bar) : "memory");
}
__device__ __forceinline__ void mbar_init(uint32_t bar, unsigned cnt){
    asm volatile("mbarrier.init.shared.b64 [%0], %1;" :: "r"(bar), "r"(cnt) : "memory");
}
__device__ __forceinline__ void mbar_expect(uint32_t bar, unsigned bytes){
    asm volatile("mbarrier.arrive.expect_tx.shared.b64 _, [%0], %1;"
        :: "r"(bar), "r"(bytes) : "memory");
}
__device__ __forceinline__ void mwait(uint32_t bar, unsigned parity){
    unsigned done;
    asm volatile("{\n\t.reg .pred p;\n\t"
        "mbarrier.try_wait.parity.acquire.cta.shared::cta.b64 p, [%1], %2;\n\t"
        "selp.b32 %0, 1, 0, p;\n\t}"
        : "=r"(done) : "r"(bar), "r"(parity) : "memory");
    if (!done){
        asm volatile("{\n\t.reg .pred P1;\n\t"
            "WL_%=:\n\t"
            "mbarrier.try_wait.parity.acquire.cta.shared::cta.b64 P1, [%0], %1, 0x989680;\n\t"
            "@P1 bra.uni WD_%=;\n\t"
            "bra.uni WL_%=;\n\t"
            "WD_%=:\n\t}"
            :: "r"(bar), "r"(parity) : "memory");
    }
}

// swizzled uint index within a packed 1024-uint block (row-pairs in 128B lines)
__device__ __forceinline__ int swz(int row, int u){
    int L = row>>1;
    int ch = (((row&1)<<2) | (u>>2)) ^ (L&7);
    return (L<<5) + (ch<<2) + (u&3);
}
// inverse: within-block index -> (row, u)
__device__ __forceinline__ void unswz(int within, int& row, int& u){
    int L = within>>5, chp = (within>>2)&7, w = within&3;
    int chunk = chp ^ (L&7);
    row = (L<<1) | (chunk>>2);
    u   = ((chunk&3)<<2) | w;
}

// ---------------- bulk-copy GEMM core -----------------------------------
// Tile (MT*32) x 64, 8 warps 2x4, NK chunks of k=32.
// Operands packed+swizzled per kchunk block; strides in uints per kchunk.
// Stage buffers: 3 x 16KB at smem offset 0; mbarriers at mb (+8 per buffer).
// accH = hi*hi; accM = lo*hi + hi*lo (scaled 2^11).
// doIter order (validated R15): loads -> MMAs (consume regs, forcing LDS
// completion) -> __syncthreads -> refill issue. Do NOT reorder: BAR.SYNC does
// not drain pending LDS reads (R16 post-mortem).
template<int MT, int NK>
__device__ __forceinline__ void gemmBulk(char* sm, uint32_t mb,
    const unsigned* __restrict__ Ah, const unsigned* __restrict__ Al,
    const unsigned* __restrict__ Bh, const unsigned* __restrict__ Bl,
    int strideA, int strideB,
    int& nu0, int& nu1, int& nu2,
    float accH[MT][2][4], float accM[MT][2][4])
{
    constexpr int AU = MT*32*16;            // uints per A block
    constexpr unsigned TXB = 8u*AU + 8192u; // bytes per stage
    const int tid = threadIdx.x, lane = tid&31, warp = tid>>5;
    const int wm = warp>>2, wn = warp&3;
    const int lr = lane>>2, lc = lane&3;
    uint32_t smb = (uint32_t)__cvta_generic_to_shared(sm);
    const unsigned* smu = (const unsigned*)sm;

    int offA[2][MT][4], offB[2][2][2];
    #pragma unroll
    for (int s=0;s<2;s++){
        #pragma unroll
        for (int mt=0; mt<MT; mt++)
            #pragma unroll
            for (int j=0;j<4;j++){
                int row = (wm*MT + mt)*16 + ((j&1)<<3) + lr;
                int u = (s<<3) + ((j>>1)<<2) + lc;
                offA[s][mt][j] = swz(row, u);
            }
        #pragma unroll
        for (int nt=0; nt<2; nt++)
            #pragma unroll
            for (int j=0;j<2;j++){
                int row = wn*16 + nt*8 + lr;
                int u = (s<<3) + (j<<2) + lc;
                offB[s][nt][j] = swz(row, u);
            }
    }

    #pragma unroll
    for (int i=0;i<MT;i++)
      #pragma unroll
      for (int j=0;j<2;j++)
        #pragma unroll
        for (int e=0;e<4;e++){ accH[i][j][e]=0.f; accM[i][j][e]=0.f; }

    auto issue = [&](int ki, int buf){
        uint32_t bar = mb + (uint32_t)buf*8;
        uint32_t dst = smb + (uint32_t)buf*16384;
        mbar_expect(bar, TXB);
        cpbulk(dst,                 Ah + (size_t)ki*strideA, AU*4, bar);
        cpbulk(dst + AU*4,          Al + (size_t)ki*strideA, AU*4, bar);
        cpbulk(dst + 2*AU*4,        Bh + (size_t)ki*strideB, 4096, bar);
        cpbulk(dst + 2*AU*4 + 4096, Bl + (size_t)ki*strideB, 4096, bar);
    };

    if (tid == 0){
        asm volatile("fence.proxy.async;" ::: "memory");
        issue(0,0); issue(1,1); issue(2,2);
    }

    auto doIter = [&](int ki, int buf, int& nu){
        mwait(mb + (uint32_t)buf*8, (unsigned)(nu & 1));
        nu++;
        const unsigned* base = smu + (size_t)buf*4096;
        unsigned ah[2][MT][4], al[2][MT][4], bh[2][2][2], bl[2][2][2];
        #pragma unroll
        for (int s=0;s<2;s++){
            #pragma unroll
            for (int mt=0;mt<MT;mt++)
                #pragma unroll
                for (int j=0;j<4;j++){
                    ah[s][mt][j] = base[offA[s][mt][j]];
                    al[s][mt][j] = base[AU + offA[s][mt][j]];
                }
            #pragma unroll
            for (int nt=0;nt<2;nt++)
                #pragma unroll
                for (int j=0;j<2;j++){
                    bh[s][nt][j] = base[2*AU + offB[s][nt][j]];
                    bl[s][nt][j] = base[2*AU + 1024 + offB[s][nt][j]];
                }
        }
        #pragma unroll
        for (int mt=0; mt<MT; mt++)
          #pragma unroll
          for (int nt=0; nt<2; nt++) mma_f16(accH[mt][nt], ah[0][mt], bh[0][nt]);
        #pragma unroll
        for (int mt=0; mt<MT; mt++)
          #pragma unroll
          for (int nt=0; nt<2; nt++) mma_f16(accM[mt][nt], al[0][mt], bh[0][nt]);
        #pragma unroll
        for (int mt=0; mt<MT; mt++)
          #pragma unroll
          for (int nt=0; nt<2; nt++) mma_f16(accH[mt][nt], ah[1][mt], bh[1][nt]);
        #pragma unroll
        for (int mt=0; mt<MT; mt++)
          #pragma unroll
          for (int nt=0; nt<2; nt++) mma_f16(accM[mt][nt], ah[0][mt], bl[0][nt]);
        #pragma unroll
        for (int mt=0; mt<MT; mt++)
          #pragma unroll
          for (int nt=0; nt<2; nt++) mma_f16(accM[mt][nt], al[1][mt], bh[1][nt]);
        #pragma unroll
        for (int mt=0; mt<MT; mt++)
          #pragma unroll
          for (int nt=0; nt<2; nt++) mma_f16(accM[mt][nt], ah[1][mt], bl[1][nt]);
        __syncthreads();
        if (tid == 0 && ki+3 < NK) issue(ki+3, buf);
    };

    #pragma unroll 1
    for (int io=0; io+3<=NK; io+=3){
        doIter(io,   0, nu0);
        doIter(io+1, 1, nu1);
        doIter(io+2, 2, nu2);
    }
    if (NK % 3 == 1){
        doIter(NK-1, 0, nu0);
    } else if (NK % 3 == 2){
        doIter(NK-2, 0, nu0);
        doIter(NK-1, 1, nu1);
    }
}

// ---------------- grid barrier ----------------
__device__ __forceinline__ void gridbar(unsigned& nbar){
    __threadfence();
    __syncthreads();
    ++nbar;
    if (threadIdx.x == 0){
        asm volatile("red.release.gpu.global.add.u32 [%0], 1;" :: "l"(&g_barcnt) : "memory");
        const unsigned target = (unsigned)PCTA * nbar;
        unsigned v;
        do {
            asm volatile("ld.acquire.gpu.global.u32 %0, [%1];" : "=r"(v) : "l"(&g_barcnt) : "memory");
        } while (v < target);
    }
    __syncthreads();
}

// ---------------- prep kernels ----------------
__global__ void k_init(float* __restrict__ out, const float* __restrict__ bp){
    const long nout = (long)BATCH*SEQ*OUTD;
    for (long i = blockIdx.x*(long)blockDim.x + threadIdx.x; i < nout;
         i += (long)gridDim.x*blockDim.x){
        out[i] = bp[i % OUTD];
        if (i < (long)BATCH*HID) g_c32[i] = 0.f;
        if (i < (long)BATCH*HID/2){ g_CPh[i] = 0u; g_CPl[i] = 0u; }
        if (i == 0) g_barcnt = 0u;
    }
}

__global__ void k_prep(const float* __restrict__ Wr, const float* __restrict__ Wu,
                       const float* __restrict__ Wc){
    const long N1 = 2048L*512;       // WruP
    const long N2 = 1024L*512;       // WcP
    const long N3 = 48L*XNK*1024;    // WxP
    for (long i = blockIdx.x*(long)blockDim.x + threadIdx.x; i < N1+N2+N3;
         i += (long)gridDim.x*blockDim.x){
        float v0, v1; unsigned *dh, *dl; long j;
        if (i < N1 + N2){
            const bool isRu = (i < N1);
            j = isRu ? i : (i - N1);
            int blk    = (int)(j>>10);
            int ntile  = blk>>5;
            int kch    = blk&31;
            int row, u; unswz((int)(j&1023), row, u);
            int n   = ntile*64 + row;
            int k0  = kch*32 + u*2;
            const float* W; int nn;
            if (isRu){ W = (n < 1024) ? Wr : Wu; nn = (n < 1024) ? n : n-1024;
                       dh = g_WruPh; dl = g_WruPl; }
            else     { W = Wc; nn = n; dh = g_WcPh; dl = g_WcPl; }
            v0 = W[(long)nn*CAT + k0];
            v1 = W[(long)nn*CAT + k0+1];
        } else {
            j = i - N1 - N2;
            int blk = (int)(j>>10);
            int ntg = blk / XNK;
            int kch = blk - ntg*XNK;
            int row, u; unswz((int)(j&1023), row, u);
            int g = ntg >> 4;
            int h = (ntg & 15)*64 + row;
            int k0 = kch*32 + u*2;
            const float* W = (g==0)?Wr:((g==1)?Wu:Wc);
            v0 = (k0   < EMBD) ? W[(long)h*CAT + HID + k0]   : 0.f;
            v1 = (k0+1 < EMBD) ? W[(long)h*CAT + HID + k0+1] : 0.f;
            dh = g_WxPh; dl = g_WxPl;
        }
        unsigned hi, lo; split_pair(v0, v1, hi, lo);
        dh[j] = hi; dl[j] = lo;
    }
}

__global__ void k_gather(const int* __restrict__ x, const float* __restrict__ emb){
    const long total = (long)512*XNK*1024;
    for (long i = blockIdx.x*(long)blockDim.x + threadIdx.x; i < total;
         i += (long)gridDim.x*blockDim.x){
        int blk = (int)(i>>10);
        int mtile = blk / XNK;
        int kch = blk - mtile*XNK;
        int row, u; unswz((int)(i&1023), row, u);
        int r = mtile*64 + row;
        int k0 = kch*32 + u*2;
        const float* er = emb + (size_t)x[r]*EMBD;
        float v0 = (k0   < EMBD) ? er[k0]   : 0.f;
        float v1 = (k0+1 < EMBD) ? er[k0+1] : 0.f;
        unsigned hi, lo; split_pair(v0, v1, hi, lo);
        g_xePh[i] = hi; g_xePl[i] = lo;
    }
}

// ---------------- x-part GEMM: bulk-copy path ----------------
extern __shared__ char dynsm[];
#define XG_MBAR 49152
#define XG_TOT  49216

__global__ void __launch_bounds__(256) k_xgemm(const float* __restrict__ br,
        const float* __restrict__ bu, const float* __restrict__ bc){
    char* sm = dynsm;
    const int tid = threadIdx.x, lane = tid&31, warp = tid>>5;
    const int wm = warp>>2, wn = warp&3;
    uint32_t smb = (uint32_t)__cvta_generic_to_shared(sm);
    const uint32_t mb = smb + XG_MBAR;
    if (tid == 0){
        mbar_init(mb, 1); mbar_init(mb+8, 1); mbar_init(mb+16, 1);
        asm volatile("fence.proxy.async;" ::: "memory");
    }
    __syncthreads();

    float accH[2][2][4], accM[2][2][4];
    int nu0=0, nu1=0, nu2=0;
    const unsigned* Ahp = g_xePh + (size_t)blockIdx.x*(XNK*1024);
    const unsigned* Alp = g_xePl + (size_t)blockIdx.x*(XNK*1024);
    const unsigned* Bhp = g_WxPh + (size_t)blockIdx.y*(XNK*1024);
    const unsigned* Blp = g_WxPl + (size_t)blockIdx.y*(XNK*1024);
    gemmBulk<2,XNK>(sm, mb, Ahp, Alp, Bhp, Blp, 1024, 1024, nu0, nu1, nu2, accH, accM);

    const int m0 = blockIdx.x*64;
    const int g  = blockIdx.y >> 4;
    const int n0 = (blockIdx.y & 15)*64;
    const float* bias = (g==0)?br:((g==1)?bu:bc);
    float* Xg = g_X + (size_t)g*SEQ*BATCH*HID;
    #pragma unroll
    for (int mt=0;mt<2;mt++)
      #pragma unroll
      for (int nt=0;nt<2;nt++)
        #pragma unroll
        for (int ep=0;ep<2;ep++){
            const int r = m0 + (wm*2+mt)*16 + (lane>>2) + ep*8;
            const int c = n0 + (wn*2+nt)*8 + (lane&3)*2;
            const int b = r>>7, t = r&127;
            float2 o;
            o.x = accH[mt][nt][ep*2+0] + accM[mt][nt][ep*2+0]*LINV + bias[c];
            o.y = accH[mt][nt][ep*2+1] + accM[mt][nt][ep*2+1]*LINV + bias[c+1];
            *(float2*)(Xg + ((size_t)t*BATCH + b)*HID + c) = o;
        }
}

// ---------------- persistent recurrence: bulk-copy pipeline ------------------
// smem: 3 x 16KB stages [0, 49152) | mbarriers 49152 | Wps 49216 | Cs 54336
#define SM_MBAR 49152
#define SM_WPS  49216
#define SM_CS   54336
#define SM_TOT  62656

__global__ void __launch_bounds__(256,1) k_recur(float* __restrict__ out,
                                                 const float* __restrict__ Wp){
    char*  sm  = dynsm;
    float* Wps = (float*)(dynsm + SM_WPS);          // 20 x 64
    float* Cs  = (float*)(dynsm + SM_CS);           // 32 x 65
    const int cta = blockIdx.x;
    const int tid = threadIdx.x, lane = tid&31, warp = tid>>5;
    const int wm = warp>>2, wn = warp&3;
    uint32_t smb = (uint32_t)__cvta_generic_to_shared(sm);
    const uint32_t mb = smb + SM_MBAR;

    const int mA = (cta&3)*64,  nA = (cta>>2)*64;   // phase A: 4m x 32n tiles (64x64)
    const int mB = (cta&7)*32,  nB = (cta>>3)*64;   // phase B: 8m x 16n tiles (32x64)

    if (tid == 0){
        mbar_init(mb,    1);
        mbar_init(mb+8,  1);
        mbar_init(mb+16, 1);
        asm volatile("fence.proxy.async;" ::: "memory");
    }
    for (int i = tid; i < OUTD*64; i += 256){
        int o = i>>6, hh = i&63;
        Wps[o*64+hh] = Wp[(size_t)o*HID + nB + hh];
    }
    __syncthreads();

    const unsigned* Aa_h = g_CPh  + (size_t)(cta&3)*1024;
    const unsigned* Aa_l = g_CPl  + (size_t)(cta&3)*1024;
    const unsigned* Ba_h = g_WruPh + (size_t)(cta>>2)*32768;
    const unsigned* Ba_l = g_WruPl + (size_t)(cta>>2)*32768;
    const unsigned* Ab_h = g_RCPh + (size_t)(cta&7)*512;
    const unsigned* Ab_l = g_RCPl + (size_t)(cta&7)*512;
    const unsigned* Bb_h = g_WcPh + (size_t)(cta>>3)*32768;
    const unsigned* Bb_l = g_WcPl + (size_t)(cta>>3)*32768;

    int nu0 = 0, nu1 = 0, nu2 = 0;
    unsigned nbar = 0;
    for (int t=0; t<SEQ; ++t){
        // ---- phase A: r,u gates (64x64, MT=2) ----
        {
            float accH[2][2][4], accM[2][2][4];
            gemmBulk<2,32>(sm, mb, Aa_h, Aa_l, Ba_h, Ba_l, 4096, 1024,
                           nu0, nu1, nu2, accH, accM);
            const bool isU = (nA >= HID);
            const float* Xg = g_X + (size_t)((isU?1:0)*SEQ + t)*BATCH*HID;
            #pragma unroll
            for (int mt=0;mt<2;mt++)
              #pragma unroll
              for (int nt=0;nt<2;nt++)
                #pragma unroll
                for (int ep=0;ep<2;ep++){
                    const int b = mA + (wm*2+mt)*16 + (lane>>2) + ep*8;
                    const int c = nA + (wn*2+nt)*8 + (lane&3)*2;
                    const int h = c & (HID-1);
                    const size_t idx = (size_t)b*HID + h;
                    float2 xv = *(const float2*)(Xg + idx);
                    float p0 = accH[mt][nt][ep*2+0] + accM[mt][nt][ep*2+0]*LINV + xv.x;
                    float p1 = accH[mt][nt][ep*2+1] + accM[mt][nt][ep*2+1]*LINV + xv.y;
                    float s0 = 1.f/(1.f+__expf(-p0));
                    float s1 = 1.f/(1.f+__expf(-p1));
                    if (isU){
                        __stcg((float2*)(g_u+idx), make_float2(s0,s1));
                    } else {
                        float2 cp = __ldcg((const float2*)(g_c32+idx));
                        unsigned hi, lo; split_pair(s0*cp.x, s1*cp.y, hi, lo);
                        // packed RC layout: [kchunk][mtile8][512], swizzled
                        int kch = h>>5, mtl = b>>5, row = b&31, uu = (h&31)>>1;
                        size_t pidx = (size_t)(kch*8 + mtl)*512 + swz(row, uu);
                        __stcg(&g_RCPh[pidx], hi);
                        __stcg(&g_RCPl[pidx], lo);
                    }
                }
        }
        gridbar(nbar);
        // ---- phase B: candidate + state update + y (32x64, MT=1) ----
        {
            float accH[1][2][4], accM[1][2][4];
            gemmBulk<1,32>(sm, mb, Ab_h, Ab_l, Bb_h, Bb_l, 4096, 1024,
                           nu0, nu1, nu2, accH, accM);
            const float* Xg = g_X + (size_t)(2*SEQ + t)*BATCH*HID;
            #pragma unroll
            for (int nt=0;nt<2;nt++)
              #pragma unroll
              for (int ep=0;ep<2;ep++){
                  const int b = mB + wm*16 + (lane>>2) + ep*8;
                  const int c = nB + (wn*2+nt)*8 + (lane&3)*2;
                  const size_t idx = (size_t)b*HID + c;
                  float2 xv = *(const float2*)(Xg + idx);
                  float2 uv = __ldcg((const float2*)(g_u+idx));
                  float2 cp = __ldcg((const float2*)(g_c32+idx));
                  float cc0 = tanhf(accH[0][nt][ep*2+0] + accM[0][nt][ep*2+0]*LINV + xv.x);
                  float cc1 = tanhf(accH[0][nt][ep*2+1] + accM[0][nt][ep*2+1]*LINV + xv.y);
                  float cn0 = uv.x*cc0 + (1.f-uv.x)*cp.x;
                  float cn1 = uv.y*cc1 + (1.f-uv.y)*cp.y;
                  __stcg((float2*)(g_c32+idx), make_float2(cn0,cn1));
                  unsigned hi, lo; split_pair(cn0, cn1, hi, lo);
                  // packed C layout: [kchunk][mtile4][1024], swizzled
                  int kch = c>>5, mtl = b>>6, row = b&63, uu = (c&31)>>1;
                  size_t pidx = (size_t)(kch*4 + mtl)*1024 + swz(row, uu);
                  __stcg(&g_CPh[pidx], hi);
                  __stcg(&g_CPl[pidx], lo);
                  Cs[(b-mB)*65 + (c-nB)  ] = cn0;
                  Cs[(b-mB)*65 + (c-nB)+1] = cn1;
              }
            __syncthreads();
            const int bl = tid & 31, og = tid >> 5;
            #pragma unroll
            for (int j=og; j<OUTD; j+=8){
                float s = 0.f;
                #pragma unroll
                for (int hh=0; hh<64; ++hh)
                    s += Cs[bl*65+hh] * Wps[j*64+hh];
                atomicAdd(&out[((size_t)(mB+bl)*SEQ + t)*OUTD + j], s);
            }
        }
        gridbar(nbar);
    }
}

// ---------------- launch ----------------
extern "C" void kernel_launch(void* const* d_in, const int* in_sizes, int n_in,
                              void* d_out, int out_size){
    const int*   x   = (const int*)  d_in[0];
    const float* emb = (const float*)d_in[1];
    const float* Wr  = (const float*)d_in[2];
    const float* br  = (const float*)d_in[3];
    const float* Wu  = (const float*)d_in[4];
    const float* bu  = (const float*)d_in[5];
    const float* Wc  = (const float*)d_in[6];
    const float* bc  = (const float*)d_in[7];
    const float* Wp  = (const float*)d_in[8];
    const float* bp  = (const float*)d_in[9];
    float* out = (float*)d_out;
    (void)in_sizes; (void)n_in; (void)out_size;

    static int attr_done = 0;
    if (!attr_done){
        cudaFuncSetAttribute(k_xgemm, cudaFuncAttributeMaxDynamicSharedMemorySize, XG_TOT);
        cudaFuncSetAttribute(k_recur, cudaFuncAttributeMaxDynamicSharedMemorySize, SM_TOT);
        attr_done = 1;
    }

    k_init<<<512, 256>>>(out, bp);
    k_prep<<<1024, 256>>>(Wr, Wu, Wc);
    k_gather<<<2048, 256>>>(x, emb);
    k_xgemm<<<dim3(512,48), 256, XG_TOT>>>(br, bu, bc);
    k_recur<<<PCTA, 256, SM_TOT>>>(out, Wp);
}